// round 16
// baseline (speedup 1.0000x reference)
#include <cuda_runtime.h>
#include <math.h>

// ---------------- problem constants ----------------
#define B_   2
#define L_   1024
#define DM_  512
#define DI_  1024
#define H_   8
#define HD_  128
#define N_   32
#define NH_  16
#define G_   37
#define ROWS_ (B_*L_)            // 2048
#define NPROJ (3*DI_ + H_*N_)    // 3328
#define NGATE (H_*G_)            // 296

typedef unsigned long long u64;

// ---------------- scratch (static device globals; no allocation) ----------------
__device__ float g_xn   [ROWS_ * DM_];
__device__ float g_proj [ROWS_ * NPROJ];
__device__ float g_xconv[ROWS_ * DI_];
__device__ float g_gates[ROWS_ * NGATE];
__device__ float g_are  [ROWS_ * H_ * NH_];
__device__ float g_aim  [ROWS_ * H_ * NH_];
__device__ float g_vg   [ROWS_ * H_ * N_];
__device__ float g_beta [ROWS_ * H_];
__device__ float g_selc [ROWS_ * H_];
__device__ float g_Q    [ROWS_ * DI_];
__device__ float g_Kn   [ROWS_ * DI_];
__device__ float g_Qn   [ROWS_ * DI_];
__device__ float g_retr [ROWS_ * (H_*N_)];
__device__ float g_y    [ROWS_ * DI_];
__device__ float g_y2   [ROWS_ * DI_];
// per (b, l/4, h): 16 normalized Gram scalars:
// [G01,G02,G03,G12,G13,G23, P00,P01,P02,P03,P11,P12,P13,P22,P23,P33]
__device__ float g_cd4 [(ROWS_/4) * H_ * 16];
__device__ float g_gnsum[B_ * 8];
__device__ float g_gnsq [B_ * 8];
__device__ int   g_qflag;   // 1 if q_w == identity

// ---------------- helpers ----------------
__device__ __forceinline__ float sigm(float x) { return 1.0f / (1.0f + expf(-x)); }
__device__ __forceinline__ float softplusf(float x) { return (x > 20.0f) ? x : log1pf(expf(x)); }
__device__ __forceinline__ float siluf(float x) { return x * sigm(x); }
__device__ __forceinline__ float dot4(float4 a, float4 b) {
    return a.x*b.x + a.y*b.y + a.z*b.z + a.w*b.w;
}

__device__ __forceinline__ void mma_tf32(float* c, const unsigned* a, const unsigned* b) {
    asm volatile("mma.sync.aligned.m16n8k8.row.col.f32.tf32.tf32.f32 "
        "{%0,%1,%2,%3}, {%4,%5,%6,%7}, {%8,%9}, {%0,%1,%2,%3};"
        : "+f"(c[0]), "+f"(c[1]), "+f"(c[2]), "+f"(c[3])
        : "r"(a[0]), "r"(a[1]), "r"(a[2]), "r"(a[3]), "r"(b[0]), "r"(b[1]));
}
__device__ __forceinline__ void cp16(unsigned smem_addr, const float* gptr, unsigned srcsz) {
    asm volatile("cp.async.cg.shared.global [%0], [%1], 16, %2;"
        :: "r"(smem_addr), "l"(gptr), "r"(srcsz));
}
// packed f32x2 ops
__device__ __forceinline__ u64 pk2(float lo, float hi) {
    u64 r; asm("mov.b64 %0, {%1, %2};" : "=l"(r) : "f"(lo), "f"(hi)); return r;
}
__device__ __forceinline__ void upk(u64 v, float& lo, float& hi) {
    asm("mov.b64 {%0, %1}, %2;" : "=f"(lo), "=f"(hi) : "l"(v));
}
__device__ __forceinline__ u64 fma2(u64 a, u64 b, u64 c) {
    u64 d; asm("fma.rn.f32x2 %0, %1, %2, %3;" : "=l"(d) : "l"(a), "l"(b), "l"(c)); return d;
}
__device__ __forceinline__ u64 mul2(u64 a, u64 b) {
    u64 d; asm("mul.rn.f32x2 %0, %1, %2;" : "=l"(d) : "l"(a), "l"(b)); return d;
}
__device__ __forceinline__ float hsum2(u64 v) {
    float lo, hi; upk(v, lo, hi); return lo + hi;
}
__device__ __forceinline__ float red32(float v) {
    v += __shfl_xor_sync(0xffffffffu, v, 1);
    v += __shfl_xor_sync(0xffffffffu, v, 2);
    v += __shfl_xor_sync(0xffffffffu, v, 4);
    v += __shfl_xor_sync(0xffffffffu, v, 8);
    v += __shfl_xor_sync(0xffffffffu, v, 16);
    return v;
}
// complex scalar helpers
#define CMR(ar,ai,br,bi) ((ar)*(br)-(ai)*(bi))
#define CMI(ar,ai,br,bi) ((ar)*(bi)+(ai)*(br))

// ---------------- init kernel (qflag=1, gn stats=0) ----------------
__global__ void k_init() {
    if (threadIdx.x == 0) g_qflag = 1;
    if (threadIdx.x < B_ * 8) { g_gnsum[threadIdx.x] = 0.f; g_gnsq[threadIdx.x] = 0.f; }
}

// ---------------- fused RMSNorm + q_w identity check ----------------
__global__ void k_normcheck(const float* __restrict__ x, const float* __restrict__ w,
                            const float* __restrict__ qw) {
    int blk = blockIdx.x;
    int t = threadIdx.x;
    if (blk < ROWS_) {
        const float* xr = x + (size_t)blk * DM_;
        float s = 0.f;
        for (int i = t; i < DM_; i += 128) { float v = xr[i]; s += v * v; }
        #pragma unroll
        for (int off = 16; off; off >>= 1) s += __shfl_xor_sync(0xffffffffu, s, off);
        __shared__ float sm[4];
        if ((t & 31) == 0) sm[t >> 5] = s;
        __syncthreads();
        s = sm[0] + sm[1] + sm[2] + sm[3];
        float r = rsqrtf(s * (1.0f / DM_) + 1e-5f);
        float* o = g_xn + (size_t)blk * DM_;
        for (int i = t; i < DM_; i += 128) o[i] = xr[i] * r * w[i];
    } else {
        int i = (blk - ROWS_) * 128 + t;
        if (i < (DI_ * DI_ / 4)) {
            float4 v = ((const float4*)qw)[i];
            int base = i * 4;
            bool ok = true;
            #pragma unroll
            for (int e = 0; e < 4; e++) {
                int idx = base + e;
                int r = idx >> 10, c = idx & 1023;
                float want = (r == c) ? 1.0f : 0.0f;
                float got = (e == 0) ? v.x : (e == 1) ? v.y : (e == 2) ? v.z : v.w;
                if (got != want) ok = false;
            }
            if (!ok) g_qflag = 0;
        }
    }
}

// ---------------- TF32 tensor-core TN GEMM, 4-stage cp.async pipeline ----------------
#define SSTR 20
#define STAGES 4
template<int BN>
__global__ __launch_bounds__(256) void k_gemm_tf32(
    const float* __restrict__ A, const float* __restrict__ Bm,
    const float* __restrict__ bias, const float* __restrict__ addend,
    float* __restrict__ C, int M, int N, int K, const int* __restrict__ skip,
    float* __restrict__ gnsum, float* __restrict__ gnsq)
{
    if (skip && *skip) return;
    extern __shared__ __align__(16) unsigned sdyn[];
    unsigned* As = sdyn;
    unsigned* Bs = sdyn + STAGES * 128 * SSTR;

    constexpr int WN = BN / 2;
    constexpr int NF = WN / 8;

    int tid  = threadIdx.x;
    int lane = tid & 31;
    int wid  = tid >> 5;
    int wm = wid & 3;
    int wn = wid >> 2;
    int bm = blockIdx.y * 128, bn = blockIdx.x * BN;

    int arow = tid >> 2;
    int acol = (tid & 3) << 2;

    float acc[2][NF][4];
    #pragma unroll
    for (int i = 0; i < 2; i++)
        #pragma unroll
        for (int j = 0; j < NF; j++)
            #pragma unroll
            for (int q = 0; q < 4; q++) acc[i][j][q] = 0.f;

    const float* Ap0 = A + (size_t)(bm + arow) * K + acol;
    const float* Ap1 = Ap0 + (size_t)64 * K;
    const float* Bp0 = Bm + (size_t)(bn + arow) * K + acol;
    const float* Bp1 = Bp0 + (size_t)64 * K;
    unsigned sv0 = ((bn + arow) < N) ? 16u : 0u;
    unsigned sv1 = ((bn + arow + 64) < N) ? 16u : 0u;

    unsigned sA0 = (unsigned)__cvta_generic_to_shared(&As[0]) + (arow * SSTR + acol) * 4;
    unsigned sA1 = sA0 + 64 * SSTR * 4;
    unsigned sB0 = (unsigned)__cvta_generic_to_shared(&Bs[0]) + (arow * SSTR + acol) * 4;
    unsigned sB1 = sB0 + 64 * SSTR * 4;
    const unsigned stA = 128 * SSTR * 4;
    const unsigned stB = BN * SSTR * 4;

    int ntiles = K >> 4;

    // prime 3 stages
    #pragma unroll
    for (int s = 0; s < 3; s++) {
        int k0 = s * 16;
        if (s < 32) {  // always true; keeps compiler happy on small K
            cp16(sA0 + s * stA, Ap0 + k0, (s < ntiles) ? 16u : 0u);
            cp16(sA1 + s * stA, Ap1 + k0, (s < ntiles) ? 16u : 0u);
            cp16(sB0 + s * stB, Bp0 + k0, (s < ntiles) ? sv0 : 0u);
            if (BN == 128) cp16(sB1 + s * stB, Bp1 + k0, (s < ntiles) ? sv1 : 0u);
        }
        asm volatile("cp.async.commit_group;");
    }

    int rA = wm * 32 + (lane >> 2);
    int rB = wn * WN + (lane >> 2);
    int cKl = lane & 3;

    int stage = 0;
    for (int t = 0; t < ntiles; t++) {
        asm volatile("cp.async.wait_group 2;");
        __syncthreads();
        // issue tile t+3 (stage (t+3)%4 was last read at iter t-1, complete)
        {
            int s3 = (t + 3) & 3;
            int k0 = (t + 3) * 16;
            bool ok = (t + 3 < ntiles);
            cp16(sA0 + s3 * stA, Ap0 + (ok ? k0 : 0), ok ? 16u : 0u);
            cp16(sA1 + s3 * stA, Ap1 + (ok ? k0 : 0), ok ? 16u : 0u);
            cp16(sB0 + s3 * stB, Bp0 + (ok ? k0 : 0), ok ? sv0 : 0u);
            if (BN == 128) cp16(sB1 + s3 * stB, Bp1 + (ok ? k0 : 0), ok ? sv1 : 0u);
        }
        asm volatile("cp.async.commit_group;");

        const unsigned* Asb = As + stage * 128 * SSTR;
        const unsigned* Bsb = Bs + stage * BN * SSTR;
        #pragma unroll
        for (int ks = 0; ks < 2; ks++) {
            int c0 = ks * 8 + cKl;
            unsigned af[2][4];
            #pragma unroll
            for (int mf = 0; mf < 2; mf++) {
                int r0 = rA + mf * 16;
                af[mf][0] = Asb[r0 * SSTR + c0];
                af[mf][1] = Asb[(r0 + 8) * SSTR + c0];
                af[mf][2] = Asb[r0 * SSTR + c0 + 4];
                af[mf][3] = Asb[(r0 + 8) * SSTR + c0 + 4];
            }
            unsigned bf[NF][2];
            #pragma unroll
            for (int nf = 0; nf < NF; nf++) {
                int n0 = rB + nf * 8;
                bf[nf][0] = Bsb[n0 * SSTR + c0];
                bf[nf][1] = Bsb[n0 * SSTR + c0 + 4];
            }
            #pragma unroll
            for (int mf = 0; mf < 2; mf++)
                #pragma unroll
                for (int nf = 0; nf < NF; nf++)
                    mma_tf32(acc[mf][nf], af[mf], bf[nf]);
        }
        stage = (stage + 1) & 3;
    }

    #pragma unroll
    for (int mf = 0; mf < 2; mf++) {
        int row = bm + wm * 32 + mf * 16 + (lane >> 2);
        #pragma unroll
        for (int nf = 0; nf < NF; nf++) {
            int col = bn + wn * WN + nf * 8 + ((lane & 3) << 1);
            if (col < N) {
                float b0v = bias ? bias[col] : 0.f;
                float b1v = bias ? bias[col + 1] : 0.f;
                float v0 = acc[mf][nf][0] + b0v;
                float v1 = acc[mf][nf][1] + b1v;
                float v2 = acc[mf][nf][2] + b0v;
                float v3 = acc[mf][nf][3] + b1v;
                size_t i0 = (size_t)row * N + col;
                size_t i1 = (size_t)(row + 8) * N + col;
                if (addend) {
                    v0 += addend[i0]; v1 += addend[i0 + 1];
                    v2 += addend[i1]; v3 += addend[i1 + 1];
                }
                *(float2*)(C + i0) = make_float2(v0, v1);
                *(float2*)(C + i1) = make_float2(v2, v3);
            }
        }
    }

    if (gnsum) {
        float s = 0.f, ss = 0.f;
        #pragma unroll
        for (int mf = 0; mf < 2; mf++)
            #pragma unroll
            for (int nf = 0; nf < NF; nf++)
                #pragma unroll
                for (int q = 0; q < 4; q++) {
                    float v = acc[mf][nf][q];
                    if (bias) v += bias[bn + wn * WN + nf * 8 + ((lane & 3) << 1) + (q & 1)];
                    s += v; ss += v * v;
                }
        #pragma unroll
        for (int off = 16; off; off >>= 1) {
            s  += __shfl_xor_sync(0xffffffffu, s,  off);
            ss += __shfl_xor_sync(0xffffffffu, ss, off);
        }
        __shared__ float w1[8], w2[8];
        if (lane == 0) { w1[wid] = s; w2[wid] = ss; }
        __syncthreads();
        if (tid == 0) {
            float S = 0.f, SS = 0.f;
            #pragma unroll
            for (int i = 0; i < 8; i++) { S += w1[i]; SS += w2[i]; }
            int bg = (blockIdx.y >> 3) * 8 + blockIdx.x;
            atomicAdd(&gnsum[bg], S);
            atomicAdd(&gnsq[bg], SS);
        }
    }
}

// ---------------- causal depthwise conv (K=4) + SiLU ----------------
__global__ void k_conv(const float* __restrict__ cw, const float* __restrict__ cb) {
    int i = blockIdx.x * 256 + threadIdx.x;
    if (i >= ROWS_ * DI_) return;
    int m = i >> 10;
    int d = i & 1023;
    int l = m & (L_ - 1);
    int base = m - l;
    float acc = cb[d];
    float w0 = cw[d*4+0], w1 = cw[d*4+1], w2 = cw[d*4+2], w3 = cw[d*4+3];
    if (l >= 3) acc = fmaf(w0, g_proj[(size_t)(base + l - 3) * NPROJ + DI_ + d], acc);
    if (l >= 2) acc = fmaf(w1, g_proj[(size_t)(base + l - 2) * NPROJ + DI_ + d], acc);
    if (l >= 1) acc = fmaf(w2, g_proj[(size_t)(base + l - 1) * NPROJ + DI_ + d], acc);
    acc = fmaf(w3, g_proj[(size_t)m * NPROJ + DI_ + d], acc);
    g_xconv[i] = siluf(acc);
}

// ---------------- fused dynamics + l2norm + quad Gram scalars ----------------
#define NDYN ((ROWS_ * H_) / 256)                    // 64
#define NL2  (((ROWS_/4) * H_ * 32) / 256)           // 512
__global__ void k_dynl2(const float* __restrict__ v_first,
                        const float* __restrict__ log_dt,
                        const float* __restrict__ vrg) {
    int blk = blockIdx.x;
    if (blk < NDYN) {
        int i = blk * 256 + threadIdx.x;   // i = row*H + h
        int h = i & (H_ - 1);
        const float* g = g_gates + (size_t)i * G_;
        float sB = g[32], sC = g[33], sdt = g[34], braw = g[35], rg = g[36];
        float dt = softplusf(sdt + log_dt[h]) + 1e-3f;
        float hdt = 0.5f * dt;
        float r = sigm(rg);
        float beta = sigm(braw) * sigm(sB);
        float freq = expf(-(float)h * (logf(10000.0f) / (float)H_));
        float nu = sigm(vrg[h]);
        g_beta[i] = beta;
        g_selc[i] = sigm(sC);
        int row = i >> 3;
        const float* vrow = g_proj + (size_t)row * NPROJ + 3 * DI_ + h * N_;
        const float* vfr  = v_first + (size_t)i * N_;
        #pragma unroll
        for (int n = 0; n < NH_; n++) {
            float lam_re = -softplusf(g[n]);
            float lam_im = g[16 + n] + freq;
            float nr = 1.f + hdt * lam_re, ni = hdt * lam_im;
            float dr = 1.f - hdt * lam_re, di = -hdt * lam_im;
            float den = dr * dr + di * di;
            float are = (nr * dr + ni * di) / den * r;
            float aim = (ni * dr - nr * di) / den * r;
            float vp = sqrtf(fmaxf(1.f - (are * are + aim * aim), 1e-6f));
            g_are[(size_t)i * NH_ + n] = are;
            g_aim[(size_t)i * NH_ + n] = aim;
            float v0 = vrow[2*n],   vf0 = vfr[2*n];
            float v1 = vrow[2*n+1], vf1 = vfr[2*n+1];
            g_vg[(size_t)i * N_ + 2*n]     = (vf0 + nu * (v0 - vf0)) * vp;
            g_vg[(size_t)i * N_ + 2*n + 1] = (vf1 + nu * (v1 - vf1)) * vp;
        }
        return;
    }
    // l2qkx4 part
    int idx = (((blk - NDYN) * 256 + threadIdx.x) >> 5);  // row4*H + h
    int lane = threadIdx.x & 31;
    if (idx >= (ROWS_/4) * H_) return;
    int row4 = idx >> 3, h = idx & 7;
    int r0 = row4 * 4;
    const float* qbase = g_qflag ? g_xconv : g_Q;
    float4 k[4], q[4];
    #pragma unroll
    for (int l = 0; l < 4; l++) {
        k[l] = ((const float4*)(g_proj + (size_t)(r0 + l) * NPROJ + 2 * DI_ + h * HD_))[lane];
        q[l] = ((const float4*)(qbase  + (size_t)(r0 + l) * DI_ + h * HD_))[lane];
    }
    float r[24];
    #pragma unroll
    for (int l = 0; l < 4; l++) r[l] = dot4(k[l], k[l]);
    #pragma unroll
    for (int l = 0; l < 4; l++) r[4 + l] = dot4(q[l], q[l]);
    r[8]  = dot4(k[0], k[1]); r[9]  = dot4(k[0], k[2]); r[10] = dot4(k[0], k[3]);
    r[11] = dot4(k[1], k[2]); r[12] = dot4(k[1], k[3]); r[13] = dot4(k[2], k[3]);
    r[14] = dot4(k[0], q[0]); r[15] = dot4(k[0], q[1]); r[16] = dot4(k[0], q[2]); r[17] = dot4(k[0], q[3]);
    r[18] = dot4(k[1], q[1]); r[19] = dot4(k[1], q[2]); r[20] = dot4(k[1], q[3]);
    r[21] = dot4(k[2], q[2]); r[22] = dot4(k[2], q[3]);
    r[23] = dot4(k[3], q[3]);
    #pragma unroll
    for (int off = 16; off; off >>= 1) {
        #pragma unroll
        for (int i = 0; i < 24; i++) r[i] += __shfl_xor_sync(0xffffffffu, r[i], off);
    }
    float kr[4], qr[4];
    #pragma unroll
    for (int l = 0; l < 4; l++) { kr[l] = rsqrtf(r[l] + 1e-6f); qr[l] = rsqrtf(r[4+l] + 1e-6f); }
    #pragma unroll
    for (int l = 0; l < 4; l++) {
        int rh = (r0 + l) * H_ + h;
        ((float4*)(g_Kn + (size_t)rh * HD_))[lane] =
            make_float4(k[l].x*kr[l], k[l].y*kr[l], k[l].z*kr[l], k[l].w*kr[l]);
        ((float4*)(g_Qn + (size_t)rh * HD_))[lane] =
            make_float4(q[l].x*qr[l], q[l].y*qr[l], q[l].z*qr[l], q[l].w*qr[l]);
    }
    if (lane == 0) {
        float* cd = g_cd4 + (size_t)idx * 16;
        cd[0] = r[8]  * kr[0] * kr[1];
        cd[1] = r[9]  * kr[0] * kr[2];
        cd[2] = r[10] * kr[0] * kr[3];
        cd[3] = r[11] * kr[1] * kr[2];
        cd[4] = r[12] * kr[1] * kr[3];
        cd[5] = r[13] * kr[2] * kr[3];
        cd[6]  = r[14] * kr[0] * qr[0];
        cd[7]  = r[15] * kr[0] * qr[1];
        cd[8]  = r[16] * kr[0] * qr[2];
        cd[9]  = r[17] * kr[0] * qr[3];
        cd[10] = r[18] * kr[1] * qr[1];
        cd[11] = r[19] * kr[1] * qr[2];
        cd[12] = r[20] * kr[1] * qr[3];
        cd[13] = r[21] * kr[2] * qr[2];
        cd[14] = r[22] * kr[2] * qr[3];
        cd[15] = r[23] * kr[3] * qr[3];
    }
}

// ---------------- scan: 4-step WY unroll (R11 proven ordering) ----------------
// 256 chains (b,h,nh), one chain per warp (256 one-warp blocks), d=4 per lane.
#define LOADQ(P, IT) { \
    int rq_ = rh0 + (IT) * 4 * H_; \
    _Pragma("unroll") \
    for (int l_ = 0; l_ < 4; l_++) { \
        int rl_ = rq_ + l_ * H_; \
        ulonglong2 tk_ = *(const ulonglong2*)(g_Kn + (size_t)rl_ * HD_ + lane * 4); \
        kx[P][l_][0] = tk_.x; kx[P][l_][1] = tk_.y; \
        ulonglong2 tq_ = *(const ulonglong2*)(g_Qn + (size_t)rl_ * HD_ + lane * 4); \
        qx[P][l_][0] = tq_.x; qx[P][l_][1] = tq_.y; \
        ara[P][l_] = g_are[(size_t)rl_ * NH_ + nh]; \
        aia[P][l_] = g_aim[(size_t)rl_ * NH_ + nh]; \
        float2 vv_ = *(const float2*)(g_vg + (size_t)rl_ * N_ + 2 * nh); \
        vra[P][l_] = vv_.x; via[P][l_] = vv_.y; \
        beta_[P][l_] = g_beta[rl_]; sela[P][l_] = g_selc[rl_]; \
    } \
    const float4* cp_ = (const float4*)(g_cd4 + ((size_t)bofs + (IT)) * (H_ * 16) + h * 16); \
    cdA[P][0] = cp_[0]; cdA[P][1] = cp_[1]; cdA[P][2] = cp_[2]; cdA[P][3] = cp_[3]; }

#define QSTEP(P, IT) { \
    if ((IT) + 1 < L_/4) LOADQ((P)^1, (IT)+1); \
    float kSr[4], kSi[4], qSr[4], qSi[4]; \
    _Pragma("unroll") \
    for (int l_ = 0; l_ < 4; l_++) { \
        u64 t0_ = mul2(Sre2[0], kx[P][l_][0]); \
        kSr[l_] = hsum2(fma2(Sre2[1], kx[P][l_][1], t0_)); \
        u64 t1_ = mul2(Sim2[0], kx[P][l_][0]); \
        kSi[l_] = hsum2(fma2(Sim2[1], kx[P][l_][1], t1_)); \
        u64 t2_ = mul2(Sre2[0], qx[P][l_][0]); \
        qSr[l_] = hsum2(fma2(Sre2[1], qx[P][l_][1], t2_)); \
        u64 t3_ = mul2(Sim2[0], qx[P][l_][0]); \
        qSi[l_] = hsum2(fma2(Sim2[1], qx[P][l_][1], t3_)); \
    } \
    _Pragma("unroll") \
    for (int l_ = 0; l_ < 4; l_++) { \
        kSr[l_] = red32(kSr[l_]); kSi[l_] = red32(kSi[l_]); \
        qSr[l_] = red32(qSr[l_]); qSi[l_] = red32(qSi[l_]); \
    } \
    float a0r = ara[P][0], a0i = aia[P][0], a1r = ara[P][1], a1i = aia[P][1]; \
    float a2r = ara[P][2], a2i = aia[P][2], a3r = ara[P][3], a3i = aia[P][3]; \
    float A1r = CMR(a0r,a0i,a1r,a1i), A1i = CMI(a0r,a0i,a1r,a1i); \
    float A2r = CMR(A1r,A1i,a2r,a2i), A2i = CMI(A1r,A1i,a2r,a2i); \
    float A3r = CMR(A2r,A2i,a3r,a3i), A3i = CMI(A2r,A2i,a3r,a3i); \
    float t2r = CMR(a1r,a1i,a2r,a2i), t2i = CMI(a1r,a1i,a2r,a2i); \
    float t3r = CMR(t2r,t2i,a3r,a3i), t3i = CMI(t2r,t2i,a3r,a3i); \
    float u3r = CMR(a2r,a2i,a3r,a3i), u3i = CMI(a2r,a2i,a3r,a3i); \
    float G01 = cdA[P][0].x, G02 = cdA[P][0].y, G03 = cdA[P][0].z, G12 = cdA[P][0].w; \
    float G13 = cdA[P][1].x, G23 = cdA[P][1].y; \
    float P00 = cdA[P][1].z, P01 = cdA[P][1].w; \
    float P02 = cdA[P][2].x, P03 = cdA[P][2].y, P11 = cdA[P][2].z, P12 = cdA[P][2].w; \
    float P13 = cdA[P][3].x, P22 = cdA[P][3].y, P23 = cdA[P][3].z, P33 = cdA[P][3].w; \
    float e0r = beta_[P][0] * (vra[P][0] - CMR(a0r,a0i,kSr[0],kSi[0])); \
    float e0i = beta_[P][0] * (via[P][0] - CMI(a0r,a0i,kSr[0],kSi[0])); \
    float h10r = CMR(a1r,a1i,e0r,e0i), h10i = CMI(a1r,a1i,e0r,e0i); \
    float e1r = beta_[P][1] * (vra[P][1] - CMR(A1r,A1i,kSr[1],kSi[1]) - G01*h10r); \
    float e1i = beta_[P][1] * (via[P][1] - CMI(A1r,A1i,kSr[1],kSi[1]) - G01*h10i); \
    float h20r = CMR(t2r,t2i,e0r,e0i), h20i = CMI(t2r,t2i,e0r,e0i); \
    float h21r = CMR(a2r,a2i,e1r,e1i), h21i = CMI(a2r,a2i,e1r,e1i); \
    float e2r = beta_[P][2] * (vra[P][2] - CMR(A2r,A2i,kSr[2],kSi[2]) - G02*h20r - G12*h21r); \
    float e2i = beta_[P][2] * (via[P][2] - CMI(A2r,A2i,kSr[2],kSi[2]) - G02*h20i - G12*h21i); \
    float h30r = CMR(t3r,t3i,e0r,e0i), h30i = CMI(t3r,t3i,e0r,e0i); \
    float h31r = CMR(u3r,u3i,e1r,e1i), h31i = CMI(u3r,u3i,e1r,e1i); \
    float h32r = CMR(a3r,a3i,e2r,e2i), h32i = CMI(a3r,a3i,e2r,e2i); \
    float e3r = beta_[P][3] * (vra[P][3] - CMR(A3r,A3i,kSr[3],kSi[3]) - G03*h30r - G13*h31r - G23*h32r); \
    float e3i = beta_[P][3] * (via[P][3] - CMI(A3r,A3i,kSr[3],kSi[3]) - G03*h30i - G13*h31i - G23*h32i); \
    if (lane == 0) { \
        int rq_ = rh0 + (IT) * 4 * H_; \
        float y0r = CMR(a0r,a0i,qSr[0],qSi[0]) + P00*e0r; \
        float y0i = CMI(a0r,a0i,qSr[0],qSi[0]) + P00*e0i; \
        float y1r = CMR(A1r,A1i,qSr[1],qSi[1]) + P01*h10r + P11*e1r; \
        float y1i = CMI(A1r,A1i,qSr[1],qSi[1]) + P01*h10i + P11*e1i; \
        float y2r = CMR(A2r,A2i,qSr[2],qSi[2]) + P02*h20r + P12*h21r + P22*e2r; \
        float y2i = CMI(A2r,A2i,qSr[2],qSi[2]) + P02*h20i + P12*h21i + P22*e2i; \
        float y3r = CMR(A3r,A3i,qSr[3],qSi[3]) + P03*h30r + P13*h31r + P23*h32r + P33*e3r; \
        float y3i = CMI(A3r,A3i,qSr[3],qSi[3]) + P03*h30i + P13*h31i + P23*h32i + P33*e3i; \
        float s0 = sc*P00*P00, s1 = sc*P11*P11, s2 = sc*P22*P22, s3 = sc*P33*P33; \
        *(float2*)(g_retr + (size_t)rq_ * N_ + 2*nh) = \
            make_float2((y0r + s0*vra[P][0]) * sela[P][0], (y0i + s0*via[P][0]) * sela[P][0]); \
        *(float2*)(g_retr + (size_t)(rq_ + H_) * N_ + 2*nh) = \
            make_float2((y1r + s1*vra[P][1]) * sela[P][1], (y1i + s1*via[P][1]) * sela[P][1]); \
        *(float2*)(g_retr + (size_t)(rq_ + 2*H_) * N_ + 2*nh) = \
            make_float2((y2r + s2*vra[P][2]) * sela[P][2], (y2i + s2*via[P][2]) * sela[P][2]); \
        *(float2*)(g_retr + (size_t)(rq_ + 3*H_) * N_ + 2*nh) = \
            make_float2((y3r + s3*vra[P][3]) * sela[P][3], (y3i + s3*via[P][3]) * sela[P][3]); \
    } \
    u64 A3r2 = pk2(A3r, A3r), A3i2 = pk2(A3i, A3i), A3in2 = pk2(-A3i, -A3i); \
    u64 c0r2 = pk2(h30r, h30r), c0i2 = pk2(h30i, h30i); \
    u64 c1r2 = pk2(h31r, h31r), c1i2 = pk2(h31i, h31i); \
    u64 c2r2 = pk2(h32r, h32r), c2i2 = pk2(h32i, h32i); \
    u64 c3r2 = pk2(e3r, e3r),   c3i2 = pk2(e3i, e3i); \
    _Pragma("unroll") \
    for (int j_ = 0; j_ < 2; j_++) { \
        u64 rre = fma2(A3r2, Sre2[j_], mul2(A3in2, Sim2[j_])); \
        u64 rim = fma2(A3r2, Sim2[j_], mul2(A3i2, Sre2[j_])); \
        rre = fma2(c0r2, kx[P][0][j_], rre); rim = fma2(c0i2, kx[P][0][j_], rim); \
        rre = fma2(c1r2, kx[P][1][j_], rre); rim = fma2(c1i2, kx[P][1][j_], rim); \
        rre = fma2(c2r2, kx[P][2][j_], rre); rim = fma2(c2i2, kx[P][2][j_], rim); \
        Sre2[j_] = fma2(c3r2, kx[P][3][j_], rre); \
        Sim2[j_] = fma2(c3i2, kx[P][3][j_], rim); \
    } }

__global__ __launch_bounds__(32) void k_scan(const float* __restrict__ scp) {
    int wi = blockIdx.x;               // 0..255
    int nh = wi & 15;
    int h  = (wi >> 4) & 7;
    int b  = wi >> 7;
    int lane = threadIdx.x;
    float sc = scp[0];

    u64 Sre2[2], Sim2[2];
    Sre2[0] = Sre2[1] = 0ull;
    Sim2[0] = Sim2[1] = 0ull;

    int rh0 = (b * L_) * H_ + h;
    int bofs = b * (L_ / 4);

    u64 kx[2][4][2], qx[2][4][2];
    float ara[2][4], aia[2][4], vra[2][4], via[2][4], beta_[2][4], sela[2][4];
    float4 cdA[2][4];

    LOADQ(0, 0)

    for (int it = 0; it < L_/4; it += 2) {
        QSTEP(0, it)
        QSTEP(1, it + 1)
    }
}

// ---------------- group-norm apply + silu(z) gate + Dskip ----------------
__global__ void k_post(const float* __restrict__ gnw, const float* __restrict__ gnb,
                       const float* __restrict__ dskip) {
    int i = blockIdx.x * 256 + threadIdx.x;
    if (i >= ROWS_ * DI_) return;
    int m = i >> 10, c = i & 1023;
    int b = m >> 10;
    int bg = b * 8 + (c >> 7);
    const float inv = 1.0f / (float)(L_ * 128);
    float mean = g_gnsum[bg] * inv;
    float var = g_gnsq[bg] * inv - mean * mean;
    float rs = rsqrtf(var + 1e-5f);
    float yn = (g_y[i] - mean) * rs * gnw[c] + gnb[c];
    float z = g_proj[(size_t)m * NPROJ + c];
    g_y2[i] = yn * siluf(z) + dskip[c] * g_xconv[i];
}

// ---------------- launcher ----------------
extern "C" void kernel_launch(void* const* d_in, const int* in_sizes, int n_in,
                              void* d_out, int out_size) {
    const float* x        = (const float*)d_in[0];
    const float* v_first  = (const float*)d_in[1];
    const float* norm_w   = (const float*)d_in[2];
    const float* in_proj_w= (const float*)d_in[3];
    const float* in_proj_b= (const float*)d_in[4];
    const float* conv_w   = (const float*)d_in[5];
    const float* conv_b   = (const float*)d_in[6];
    const float* gate_w   = (const float*)d_in[7];
    const float* gate_b   = (const float*)d_in[8];
    const float* log_dt   = (const float*)d_in[9];
    const float* q_w      = (const float*)d_in[10];
    const float* readout_w= (const float*)d_in[11];
    const float* out_w    = (const float*)d_in[12];
    const float* gn_w     = (const float*)d_in[13];
    const float* gn_b     = (const float*)d_in[14];
    const float* dskip    = (const float*)d_in[15];
    const float* vrg      = (const float*)d_in[16];
    const float* shortcut = (const float*)d_in[17];
    float* out = (float*)d_out;

    float *p_xn, *p_proj, *p_xc, *p_Q, *p_retr, *p_y, *p_y2, *p_gates, *p_gnsum, *p_gnsq;
    int* p_qflag;
    cudaGetSymbolAddress((void**)&p_xn,    g_xn);
    cudaGetSymbolAddress((void**)&p_proj,  g_proj);
    cudaGetSymbolAddress((void**)&p_xc,    g_xconv);
    cudaGetSymbolAddress((void**)&p_gates, g_gates);
    cudaGetSymbolAddress((void**)&p_Q,     g_Q);
    cudaGetSymbolAddress((void**)&p_retr,  g_retr);
    cudaGetSymbolAddress((void**)&p_y,     g_y);
    cudaGetSymbolAddress((void**)&p_y2,    g_y2);
    cudaGetSymbolAddress((void**)&p_gnsum, g_gnsum);
    cudaGetSymbolAddress((void**)&p_gnsq,  g_gnsq);
    cudaGetSymbolAddress((void**)&p_qflag, g_qflag);

    const int smem128 = STAGES * (128 + 128) * SSTR * 4;  // 81920
    const int smem64  = STAGES * (128 + 64)  * SSTR * 4;  // 61440
    cudaFuncSetAttribute(k_gemm_tf32<128>, cudaFuncAttributeMaxDynamicSharedMemorySize, smem128);
    cudaFuncSetAttribute(k_gemm_tf32<64>,  cudaFuncAttributeMaxDynamicSharedMemorySize, smem64);

    // 0) init (qflag=1, gn stats)
    k_init<<<1, 32>>>();
    // 1) fused rmsnorm + qcheck
    k_normcheck<<<ROWS_ + (DI_ * DI_ / 4 + 127) / 128, 128>>>(x, norm_w, q_w);
    // 2) in_proj
    k_gemm_tf32<128><<<dim3((NPROJ + 127) / 128, ROWS_ / 128), 256, smem128>>>(p_xn, in_proj_w, in_proj_b, nullptr, p_proj, ROWS_, NPROJ, DM_, nullptr, nullptr, nullptr);
    // 3) conv + silu
    k_conv<<<(ROWS_ * DI_) / 256, 256>>>(conv_w, conv_b);
    // 4) gates
    k_gemm_tf32<64><<<dim3((NGATE + 63) / 64, ROWS_ / 128), 256, smem64>>>(p_xc, gate_w, gate_b, nullptr, p_gates, ROWS_, NGATE, DI_, nullptr, nullptr, nullptr);
    // 5) Q (skipped when q_w == I)
    k_gemm_tf32<128><<<dim3(DI_ / 128, ROWS_ / 128), 256, smem128>>>(p_xc, q_w, nullptr, nullptr, p_Q, ROWS_, DI_, DI_, p_qflag, nullptr, nullptr);
    // 6) fused dynamics + l2norm + quad Gram scalars
    k_dynl2<<<NDYN + NL2, 256>>>(v_first, log_dt, vrg);
    // 7) scan (WY-4)
    k_scan<<<256, 32>>>(shortcut);
    // 8) readout + fused gn stats
    k_gemm_tf32<128><<<dim3(DI_ / 128, ROWS_ / 128), 256, smem128>>>(p_retr, readout_w, nullptr, nullptr, p_y, ROWS_, DI_, H_ * N_, nullptr, p_gnsum, p_gnsq);
    // 9) gn apply + gate + skip
    k_post<<<(ROWS_ * DI_) / 256, 256>>>(gn_w, gn_b, dskip);
    // 10) out GEMM + residual
    k_gemm_tf32<64><<<dim3(DM_ / 64, ROWS_ / 128), 256, smem64>>>(p_y2, out_w, nullptr, x, out, ROWS_, DM_, DI_, nullptr, nullptr, nullptr);
}

// round 17
// speedup vs baseline: 1.0168x; 1.0168x over previous
#include <cuda_runtime.h>
#include <math.h>

// ---------------- problem constants ----------------
#define B_   2
#define L_   1024
#define DM_  512
#define DI_  1024
#define H_   8
#define HD_  128
#define N_   32
#define NH_  16
#define G_   37
#define ROWS_ (B_*L_)            // 2048
#define NPROJ (3*DI_ + H_*N_)    // 3328
#define NGATE (H_*G_)            // 296

typedef unsigned long long u64;

// ---------------- scratch (static device globals; no allocation) ----------------
__device__ float g_xn   [ROWS_ * DM_];
__device__ float g_proj [ROWS_ * NPROJ];
__device__ float g_xconv[ROWS_ * DI_];
__device__ float g_gates[ROWS_ * NGATE];
__device__ float g_are  [ROWS_ * H_ * NH_];
__device__ float g_aim  [ROWS_ * H_ * NH_];
__device__ float g_vg   [ROWS_ * H_ * N_];
__device__ float g_beta [ROWS_ * H_];
__device__ float g_selc [ROWS_ * H_];
__device__ float g_Q    [ROWS_ * DI_];
__device__ float g_Kn   [ROWS_ * DI_];
__device__ float g_Qn   [ROWS_ * DI_];
__device__ float g_retr [ROWS_ * (H_*N_)];
__device__ float g_y    [ROWS_ * DI_];
__device__ float g_y2   [ROWS_ * DI_];
// per (b, l/4, h): 16 normalized Gram scalars:
// [G01,G02,G03,G12,G13,G23, P00,P01,P02,P03,P11,P12,P13,P22,P23,P33]
__device__ float g_cd4 [(ROWS_/4) * H_ * 16];
__device__ float g_gnsum[B_ * 8];
__device__ float g_gnsq [B_ * 8];
__device__ int   g_qflag;   // 1 if q_w == identity

// ---------------- helpers ----------------
__device__ __forceinline__ float sigm(float x) { return 1.0f / (1.0f + expf(-x)); }
__device__ __forceinline__ float softplusf(float x) { return (x > 20.0f) ? x : log1pf(expf(x)); }
__device__ __forceinline__ float siluf(float x) { return x * sigm(x); }
__device__ __forceinline__ float dot4(float4 a, float4 b) {
    return a.x*b.x + a.y*b.y + a.z*b.z + a.w*b.w;
}

__device__ __forceinline__ void mma_tf32(float* c, const unsigned* a, const unsigned* b) {
    asm volatile("mma.sync.aligned.m16n8k8.row.col.f32.tf32.tf32.f32 "
        "{%0,%1,%2,%3}, {%4,%5,%6,%7}, {%8,%9}, {%0,%1,%2,%3};"
        : "+f"(c[0]), "+f"(c[1]), "+f"(c[2]), "+f"(c[3])
        : "r"(a[0]), "r"(a[1]), "r"(a[2]), "r"(a[3]), "r"(b[0]), "r"(b[1]));
}
__device__ __forceinline__ void cp16(unsigned smem_addr, const float* gptr, unsigned srcsz) {
    asm volatile("cp.async.cg.shared.global [%0], [%1], 16, %2;"
        :: "r"(smem_addr), "l"(gptr), "r"(srcsz));
}
// packed f32x2 ops
__device__ __forceinline__ u64 pk2(float lo, float hi) {
    u64 r; asm("mov.b64 %0, {%1, %2};" : "=l"(r) : "f"(lo), "f"(hi)); return r;
}
__device__ __forceinline__ void upk(u64 v, float& lo, float& hi) {
    asm("mov.b64 {%0, %1}, %2;" : "=f"(lo), "=f"(hi) : "l"(v));
}
__device__ __forceinline__ u64 fma2(u64 a, u64 b, u64 c) {
    u64 d; asm("fma.rn.f32x2 %0, %1, %2, %3;" : "=l"(d) : "l"(a), "l"(b), "l"(c)); return d;
}
__device__ __forceinline__ u64 mul2(u64 a, u64 b) {
    u64 d; asm("mul.rn.f32x2 %0, %1, %2;" : "=l"(d) : "l"(a), "l"(b)); return d;
}
__device__ __forceinline__ float hsum2(u64 v) {
    float lo, hi; upk(v, lo, hi); return lo + hi;
}
__device__ __forceinline__ float red32(float v) {
    v += __shfl_xor_sync(0xffffffffu, v, 1);
    v += __shfl_xor_sync(0xffffffffu, v, 2);
    v += __shfl_xor_sync(0xffffffffu, v, 4);
    v += __shfl_xor_sync(0xffffffffu, v, 8);
    v += __shfl_xor_sync(0xffffffffu, v, 16);
    return v;
}
// complex scalar helpers
#define CMR(ar,ai,br,bi) ((ar)*(br)-(ai)*(bi))
#define CMI(ar,ai,br,bi) ((ar)*(bi)+(ai)*(br))

// ---------------- init kernel (qflag=1, gn stats=0) ----------------
__global__ void k_init() {
    if (threadIdx.x == 0) g_qflag = 1;
    if (threadIdx.x < B_ * 8) { g_gnsum[threadIdx.x] = 0.f; g_gnsq[threadIdx.x] = 0.f; }
}

// ---------------- fused RMSNorm + q_w identity check ----------------
__global__ void k_normcheck(const float* __restrict__ x, const float* __restrict__ w,
                            const float* __restrict__ qw) {
    int blk = blockIdx.x;
    int t = threadIdx.x;
    if (blk < ROWS_) {
        const float* xr = x + (size_t)blk * DM_;
        float s = 0.f;
        for (int i = t; i < DM_; i += 128) { float v = xr[i]; s += v * v; }
        #pragma unroll
        for (int off = 16; off; off >>= 1) s += __shfl_xor_sync(0xffffffffu, s, off);
        __shared__ float sm[4];
        if ((t & 31) == 0) sm[t >> 5] = s;
        __syncthreads();
        s = sm[0] + sm[1] + sm[2] + sm[3];
        float r = rsqrtf(s * (1.0f / DM_) + 1e-5f);
        float* o = g_xn + (size_t)blk * DM_;
        for (int i = t; i < DM_; i += 128) o[i] = xr[i] * r * w[i];
    } else {
        int i = (blk - ROWS_) * 128 + t;
        if (i < (DI_ * DI_ / 4)) {
            float4 v = ((const float4*)qw)[i];
            int base = i * 4;
            bool ok = true;
            #pragma unroll
            for (int e = 0; e < 4; e++) {
                int idx = base + e;
                int r = idx >> 10, c = idx & 1023;
                float want = (r == c) ? 1.0f : 0.0f;
                float got = (e == 0) ? v.x : (e == 1) ? v.y : (e == 2) ? v.z : v.w;
                if (got != want) ok = false;
            }
            if (!ok) g_qflag = 0;
        }
    }
}

// ---------------- TF32 tensor-core TN GEMM, 3-stage cp.async pipeline ----------------
#define SSTR 20
#define STAGES 3
template<int BN>
__global__ __launch_bounds__(256) void k_gemm_tf32(
    const float* __restrict__ A, const float* __restrict__ Bm,
    const float* __restrict__ bias, const float* __restrict__ addend,
    float* __restrict__ C, int M, int N, int K, const int* __restrict__ skip,
    float* __restrict__ gnsum, float* __restrict__ gnsq)
{
    if (skip && *skip) return;
    extern __shared__ __align__(16) unsigned sdyn[];
    unsigned* As = sdyn;
    unsigned* Bs = sdyn + STAGES * 128 * SSTR;

    constexpr int WN = BN / 2;
    constexpr int NF = WN / 8;

    int tid  = threadIdx.x;
    int lane = tid & 31;
    int wid  = tid >> 5;
    int wm = wid & 3;
    int wn = wid >> 2;
    int bm = blockIdx.y * 128, bn = blockIdx.x * BN;

    int arow = tid >> 2;
    int acol = (tid & 3) << 2;

    float acc[2][NF][4];
    #pragma unroll
    for (int i = 0; i < 2; i++)
        #pragma unroll
        for (int j = 0; j < NF; j++)
            #pragma unroll
            for (int q = 0; q < 4; q++) acc[i][j][q] = 0.f;

    const float* Ap0 = A + (size_t)(bm + arow) * K + acol;
    const float* Ap1 = Ap0 + (size_t)64 * K;
    const float* Bp0 = Bm + (size_t)(bn + arow) * K + acol;
    const float* Bp1 = Bp0 + (size_t)64 * K;
    unsigned sv0 = ((bn + arow) < N) ? 16u : 0u;
    unsigned sv1 = ((bn + arow + 64) < N) ? 16u : 0u;

    unsigned sA0 = (unsigned)__cvta_generic_to_shared(&As[0]) + (arow * SSTR + acol) * 4;
    unsigned sA1 = sA0 + 64 * SSTR * 4;
    unsigned sB0 = (unsigned)__cvta_generic_to_shared(&Bs[0]) + (arow * SSTR + acol) * 4;
    unsigned sB1 = sB0 + 64 * SSTR * 4;
    const unsigned stA = 128 * SSTR * 4;
    const unsigned stB = BN * SSTR * 4;

    int ntiles = K >> 4;

    #pragma unroll
    for (int s = 0; s < 2; s++) {
        int k0 = s * 16;
        cp16(sA0 + s * stA, Ap0 + k0, 16u);
        cp16(sA1 + s * stA, Ap1 + k0, 16u);
        cp16(sB0 + s * stB, Bp0 + k0, sv0);
        if (BN == 128) cp16(sB1 + s * stB, Bp1 + k0, sv1);
        asm volatile("cp.async.commit_group;");
    }

    int rA = wm * 32 + (lane >> 2);
    int rB = wn * WN + (lane >> 2);
    int cKl = lane & 3;

    int stage = 0;
    for (int t = 0; t < ntiles; t++) {
        asm volatile("cp.async.wait_group 1;");
        __syncthreads();
        if (t + 2 < ntiles) {
            int s2 = (t + 2) % STAGES;
            int k0 = (t + 2) * 16;
            cp16(sA0 + s2 * stA, Ap0 + k0, 16u);
            cp16(sA1 + s2 * stA, Ap1 + k0, 16u);
            cp16(sB0 + s2 * stB, Bp0 + k0, sv0);
            if (BN == 128) cp16(sB1 + s2 * stB, Bp1 + k0, sv1);
        }
        asm volatile("cp.async.commit_group;");

        const unsigned* Asb = As + stage * 128 * SSTR;
        const unsigned* Bsb = Bs + stage * BN * SSTR;
        #pragma unroll
        for (int ks = 0; ks < 2; ks++) {
            int c0 = ks * 8 + cKl;
            unsigned af[2][4];
            #pragma unroll
            for (int mf = 0; mf < 2; mf++) {
                int r0 = rA + mf * 16;
                af[mf][0] = Asb[r0 * SSTR + c0];
                af[mf][1] = Asb[(r0 + 8) * SSTR + c0];
                af[mf][2] = Asb[r0 * SSTR + c0 + 4];
                af[mf][3] = Asb[(r0 + 8) * SSTR + c0 + 4];
            }
            unsigned bf[NF][2];
            #pragma unroll
            for (int nf = 0; nf < NF; nf++) {
                int n0 = rB + nf * 8;
                bf[nf][0] = Bsb[n0 * SSTR + c0];
                bf[nf][1] = Bsb[n0 * SSTR + c0 + 4];
            }
            #pragma unroll
            for (int mf = 0; mf < 2; mf++)
                #pragma unroll
                for (int nf = 0; nf < NF; nf++)
                    mma_tf32(acc[mf][nf], af[mf], bf[nf]);
        }
        stage = (stage + 1 == STAGES) ? 0 : stage + 1;
    }

    #pragma unroll
    for (int mf = 0; mf < 2; mf++) {
        int row = bm + wm * 32 + mf * 16 + (lane >> 2);
        #pragma unroll
        for (int nf = 0; nf < NF; nf++) {
            int col = bn + wn * WN + nf * 8 + ((lane & 3) << 1);
            if (col < N) {
                float b0v = bias ? bias[col] : 0.f;
                float b1v = bias ? bias[col + 1] : 0.f;
                float v0 = acc[mf][nf][0] + b0v;
                float v1 = acc[mf][nf][1] + b1v;
                float v2 = acc[mf][nf][2] + b0v;
                float v3 = acc[mf][nf][3] + b1v;
                size_t i0 = (size_t)row * N + col;
                size_t i1 = (size_t)(row + 8) * N + col;
                if (addend) {
                    v0 += addend[i0]; v1 += addend[i0 + 1];
                    v2 += addend[i1]; v3 += addend[i1 + 1];
                }
                *(float2*)(C + i0) = make_float2(v0, v1);
                *(float2*)(C + i1) = make_float2(v2, v3);
            }
        }
    }

    if (gnsum) {
        float s = 0.f, ss = 0.f;
        #pragma unroll
        for (int mf = 0; mf < 2; mf++)
            #pragma unroll
            for (int nf = 0; nf < NF; nf++)
                #pragma unroll
                for (int q = 0; q < 4; q++) {
                    float v = acc[mf][nf][q];
                    if (bias) v += bias[bn + wn * WN + nf * 8 + ((lane & 3) << 1) + (q & 1)];
                    s += v; ss += v * v;
                }
        #pragma unroll
        for (int off = 16; off; off >>= 1) {
            s  += __shfl_xor_sync(0xffffffffu, s,  off);
            ss += __shfl_xor_sync(0xffffffffu, ss, off);
        }
        __shared__ float w1[8], w2[8];
        if (lane == 0) { w1[wid] = s; w2[wid] = ss; }
        __syncthreads();
        if (tid == 0) {
            float S = 0.f, SS = 0.f;
            #pragma unroll
            for (int i = 0; i < 8; i++) { S += w1[i]; SS += w2[i]; }
            int bg = (blockIdx.y >> 3) * 8 + blockIdx.x;
            atomicAdd(&gnsum[bg], S);
            atomicAdd(&gnsq[bg], SS);
        }
    }
}

// ---------------- causal depthwise conv (K=4) + SiLU, float4 over channels ----------------
__global__ void k_conv(const float* __restrict__ cw, const float* __restrict__ cb) {
    int i = blockIdx.x * 256 + threadIdx.x;     // over ROWS_ * DI_/4
    if (i >= ROWS_ * (DI_ / 4)) return;
    int m = i >> 8;            // row = b*L + l   (DI_/4 = 256)
    int d4 = (i & 255) << 2;   // channel base
    int l = m & (L_ - 1);
    int base = m - l;
    const float4* wq = (const float4*)(cw + d4 * 4);   // 4 channels x 4 taps
    float4 wt0 = wq[0], wt1 = wq[1], wt2 = wq[2], wt3 = wq[3];
    float4 bs = *(const float4*)(cb + d4);
    const float* src = g_proj + DI_ + d4;
    float4 x3 = (l >= 3) ? *(const float4*)(src + (size_t)(base + l - 3) * NPROJ) : make_float4(0.f,0.f,0.f,0.f);
    float4 x2 = (l >= 2) ? *(const float4*)(src + (size_t)(base + l - 2) * NPROJ) : make_float4(0.f,0.f,0.f,0.f);
    float4 x1 = (l >= 1) ? *(const float4*)(src + (size_t)(base + l - 1) * NPROJ) : make_float4(0.f,0.f,0.f,0.f);
    float4 x0 = *(const float4*)(src + (size_t)m * NPROJ);
    float4 o;
    o.x = siluf(bs.x + wt0.x*x3.x + wt0.y*x2.x + wt0.z*x1.x + wt0.w*x0.x);
    o.y = siluf(bs.y + wt1.x*x3.y + wt1.y*x2.y + wt1.z*x1.y + wt1.w*x0.y);
    o.z = siluf(bs.z + wt2.x*x3.z + wt2.y*x2.z + wt2.z*x1.z + wt2.w*x0.z);
    o.w = siluf(bs.w + wt3.x*x3.w + wt3.y*x2.w + wt3.z*x1.w + wt3.w*x0.w);
    *(float4*)(g_xconv + (size_t)m * DI_ + d4) = o;
}

// ---------------- fused dynamics + l2norm + quad Gram scalars ----------------
#define NDYN ((ROWS_ * H_) / 256)                    // 64
#define NL2  (((ROWS_/4) * H_ * 32) / 256)           // 512
__global__ void k_dynl2(const float* __restrict__ v_first,
                        const float* __restrict__ log_dt,
                        const float* __restrict__ vrg) {
    int blk = blockIdx.x;
    if (blk < NDYN) {
        int i = blk * 256 + threadIdx.x;   // i = row*H + h
        int h = i & (H_ - 1);
        const float* g = g_gates + (size_t)i * G_;
        float sB = g[32], sC = g[33], sdt = g[34], braw = g[35], rg = g[36];
        float dt = softplusf(sdt + log_dt[h]) + 1e-3f;
        float hdt = 0.5f * dt;
        float r = sigm(rg);
        float beta = sigm(braw) * sigm(sB);
        float freq = expf(-(float)h * (logf(10000.0f) / (float)H_));
        float nu = sigm(vrg[h]);
        g_beta[i] = beta;
        g_selc[i] = sigm(sC);
        int row = i >> 3;
        const float* vrow = g_proj + (size_t)row * NPROJ + 3 * DI_ + h * N_;
        const float* vfr  = v_first + (size_t)i * N_;
        #pragma unroll
        for (int n = 0; n < NH_; n++) {
            float lam_re = -softplusf(g[n]);
            float lam_im = g[16 + n] + freq;
            float nr = 1.f + hdt * lam_re, ni = hdt * lam_im;
            float dr = 1.f - hdt * lam_re, di = -hdt * lam_im;
            float den = dr * dr + di * di;
            float are = (nr * dr + ni * di) / den * r;
            float aim = (ni * dr - nr * di) / den * r;
            float vp = sqrtf(fmaxf(1.f - (are * are + aim * aim), 1e-6f));
            g_are[(size_t)i * NH_ + n] = are;
            g_aim[(size_t)i * NH_ + n] = aim;
            float v0 = vrow[2*n],   vf0 = vfr[2*n];
            float v1 = vrow[2*n+1], vf1 = vfr[2*n+1];
            g_vg[(size_t)i * N_ + 2*n]     = (vf0 + nu * (v0 - vf0)) * vp;
            g_vg[(size_t)i * N_ + 2*n + 1] = (vf1 + nu * (v1 - vf1)) * vp;
        }
        return;
    }
    // l2qkx4 part
    int idx = (((blk - NDYN) * 256 + threadIdx.x) >> 5);  // row4*H + h
    int lane = threadIdx.x & 31;
    if (idx >= (ROWS_/4) * H_) return;
    int row4 = idx >> 3, h = idx & 7;
    int r0 = row4 * 4;
    const float* qbase = g_qflag ? g_xconv : g_Q;
    float4 k[4], q[4];
    #pragma unroll
    for (int l = 0; l < 4; l++) {
        k[l] = ((const float4*)(g_proj + (size_t)(r0 + l) * NPROJ + 2 * DI_ + h * HD_))[lane];
        q[l] = ((const float4*)(qbase  + (size_t)(r0 + l) * DI_ + h * HD_))[lane];
    }
    float r[24];
    #pragma unroll
    for (int l = 0; l < 4; l++) r[l] = dot4(k[l], k[l]);
    #pragma unroll
    for (int l = 0; l < 4; l++) r[4 + l] = dot4(q[l], q[l]);
    r[8]  = dot4(k[0], k[1]); r[9]  = dot4(k[0], k[2]); r[10] = dot4(k[0], k[3]);
    r[11] = dot4(k[1], k[2]); r[12] = dot4(k[1], k[3]); r[13] = dot4(k[2], k[3]);
    r[14] = dot4(k[0], q[0]); r[15] = dot4(k[0], q[1]); r[16] = dot4(k[0], q[2]); r[17] = dot4(k[0], q[3]);
    r[18] = dot4(k[1], q[1]); r[19] = dot4(k[1], q[2]); r[20] = dot4(k[1], q[3]);
    r[21] = dot4(k[2], q[2]); r[22] = dot4(k[2], q[3]);
    r[23] = dot4(k[3], q[3]);
    #pragma unroll
    for (int off = 16; off; off >>= 1) {
        #pragma unroll
        for (int i = 0; i < 24; i++) r[i] += __shfl_xor_sync(0xffffffffu, r[i], off);
    }
    float kr[4], qr[4];
    #pragma unroll
    for (int l = 0; l < 4; l++) { kr[l] = rsqrtf(r[l] + 1e-6f); qr[l] = rsqrtf(r[4+l] + 1e-6f); }
    #pragma unroll
    for (int l = 0; l < 4; l++) {
        int rh = (r0 + l) * H_ + h;
        ((float4*)(g_Kn + (size_t)rh * HD_))[lane] =
            make_float4(k[l].x*kr[l], k[l].y*kr[l], k[l].z*kr[l], k[l].w*kr[l]);
        ((float4*)(g_Qn + (size_t)rh * HD_))[lane] =
            make_float4(q[l].x*qr[l], q[l].y*qr[l], q[l].z*qr[l], q[l].w*qr[l]);
    }
    if (lane == 0) {
        float* cd = g_cd4 + (size_t)idx * 16;
        cd[0] = r[8]  * kr[0] * kr[1];
        cd[1] = r[9]  * kr[0] * kr[2];
        cd[2] = r[10] * kr[0] * kr[3];
        cd[3] = r[11] * kr[1] * kr[2];
        cd[4] = r[12] * kr[1] * kr[3];
        cd[5] = r[13] * kr[2] * kr[3];
        cd[6]  = r[14] * kr[0] * qr[0];
        cd[7]  = r[15] * kr[0] * qr[1];
        cd[8]  = r[16] * kr[0] * qr[2];
        cd[9]  = r[17] * kr[0] * qr[3];
        cd[10] = r[18] * kr[1] * qr[1];
        cd[11] = r[19] * kr[1] * qr[2];
        cd[12] = r[20] * kr[1] * qr[3];
        cd[13] = r[21] * kr[2] * qr[2];
        cd[14] = r[22] * kr[2] * qr[3];
        cd[15] = r[23] * kr[3] * qr[3];
    }
}

// ---------------- scan: 4-step WY unroll (R11 proven ordering) ----------------
// 256 chains (b,h,nh), one chain per warp (256 one-warp blocks), d=4 per lane.
#define LOADQ(P, IT) { \
    int rq_ = rh0 + (IT) * 4 * H_; \
    _Pragma("unroll") \
    for (int l_ = 0; l_ < 4; l_++) { \
        int rl_ = rq_ + l_ * H_; \
        ulonglong2 tk_ = *(const ulonglong2*)(g_Kn + (size_t)rl_ * HD_ + lane * 4); \
        kx[P][l_][0] = tk_.x; kx[P][l_][1] = tk_.y; \
        ulonglong2 tq_ = *(const ulonglong2*)(g_Qn + (size_t)rl_ * HD_ + lane * 4); \
        qx[P][l_][0] = tq_.x; qx[P][l_][1] = tq_.y; \
        ara[P][l_] = g_are[(size_t)rl_ * NH_ + nh]; \
        aia[P][l_] = g_aim[(size_t)rl_ * NH_ + nh]; \
        float2 vv_ = *(const float2*)(g_vg + (size_t)rl_ * N_ + 2 * nh); \
        vra[P][l_] = vv_.x; via[P][l_] = vv_.y; \
        beta_[P][l_] = g_beta[rl_]; sela[P][l_] = g_selc[rl_]; \
    } \
    const float4* cp_ = (const float4*)(g_cd4 + ((size_t)bofs + (IT)) * (H_ * 16) + h * 16); \
    cdA[P][0] = cp_[0]; cdA[P][1] = cp_[1]; cdA[P][2] = cp_[2]; cdA[P][3] = cp_[3]; }

#define QSTEP(P, IT) { \
    if ((IT) + 1 < L_/4) LOADQ((P)^1, (IT)+1); \
    float kSr[4], kSi[4], qSr[4], qSi[4]; \
    _Pragma("unroll") \
    for (int l_ = 0; l_ < 4; l_++) { \
        u64 t0_ = mul2(Sre2[0], kx[P][l_][0]); \
        kSr[l_] = hsum2(fma2(Sre2[1], kx[P][l_][1], t0_)); \
        u64 t1_ = mul2(Sim2[0], kx[P][l_][0]); \
        kSi[l_] = hsum2(fma2(Sim2[1], kx[P][l_][1], t1_)); \
        u64 t2_ = mul2(Sre2[0], qx[P][l_][0]); \
        qSr[l_] = hsum2(fma2(Sre2[1], qx[P][l_][1], t2_)); \
        u64 t3_ = mul2(Sim2[0], qx[P][l_][0]); \
        qSi[l_] = hsum2(fma2(Sim2[1], qx[P][l_][1], t3_)); \
    } \
    _Pragma("unroll") \
    for (int l_ = 0; l_ < 4; l_++) { \
        kSr[l_] = red32(kSr[l_]); kSi[l_] = red32(kSi[l_]); \
        qSr[l_] = red32(qSr[l_]); qSi[l_] = red32(qSi[l_]); \
    } \
    float a0r = ara[P][0], a0i = aia[P][0], a1r = ara[P][1], a1i = aia[P][1]; \
    float a2r = ara[P][2], a2i = aia[P][2], a3r = ara[P][3], a3i = aia[P][3]; \
    float A1r = CMR(a0r,a0i,a1r,a1i), A1i = CMI(a0r,a0i,a1r,a1i); \
    float A2r = CMR(A1r,A1i,a2r,a2i), A2i = CMI(A1r,A1i,a2r,a2i); \
    float A3r = CMR(A2r,A2i,a3r,a3i), A3i = CMI(A2r,A2i,a3r,a3i); \
    float t2r = CMR(a1r,a1i,a2r,a2i), t2i = CMI(a1r,a1i,a2r,a2i); \
    float t3r = CMR(t2r,t2i,a3r,a3i), t3i = CMI(t2r,t2i,a3r,a3i); \
    float u3r = CMR(a2r,a2i,a3r,a3i), u3i = CMI(a2r,a2i,a3r,a3i); \
    float G01 = cdA[P][0].x, G02 = cdA[P][0].y, G03 = cdA[P][0].z, G12 = cdA[P][0].w; \
    float G13 = cdA[P][1].x, G23 = cdA[P][1].y; \
    float P00 = cdA[P][1].z, P01 = cdA[P][1].w; \
    float P02 = cdA[P][2].x, P03 = cdA[P][2].y, P11 = cdA[P][2].z, P12 = cdA[P][2].w; \
    float P13 = cdA[P][3].x, P22 = cdA[P][3].y, P23 = cdA[P][3].z, P33 = cdA[P][3].w; \
    float e0r = beta_[P][0] * (vra[P][0] - CMR(a0r,a0i,kSr[0],kSi[0])); \
    float e0i = beta_[P][0] * (via[P][0] - CMI(a0r,a0i,kSr[0],kSi[0])); \
    float h10r = CMR(a1r,a1i,e0r,e0i), h10i = CMI(a1r,a1i,e0r,e0i); \
    float e1r = beta_[P][1] * (vra[P][1] - CMR(A1r,A1i,kSr[1],kSi[1]) - G01*h10r); \
    float e1i = beta_[P][1] * (via[P][1] - CMI(A1r,A1i,kSr[1],kSi[1]) - G01*h10i); \
    float h20r = CMR(t2r,t2i,e0r,e0i), h20i = CMI(t2r,t2i,e0r,e0i); \
    float h21r = CMR(a2r,a2i,e1r,e1i), h21i = CMI(a2r,a2i,e1r,e1i); \
    float e2r = beta_[P][2] * (vra[P][2] - CMR(A2r,A2i,kSr[2],kSi[2]) - G02*h20r - G12*h21r); \
    float e2i = beta_[P][2] * (via[P][2] - CMI(A2r,A2i,kSr[2],kSi[2]) - G02*h20i - G12*h21i); \
    float h30r = CMR(t3r,t3i,e0r,e0i), h30i = CMI(t3r,t3i,e0r,e0i); \
    float h31r = CMR(u3r,u3i,e1r,e1i), h31i = CMI(u3r,u3i,e1r,e1i); \
    float h32r = CMR(a3r,a3i,e2r,e2i), h32i = CMI(a3r,a3i,e2r,e2i); \
    float e3r = beta_[P][3] * (vra[P][3] - CMR(A3r,A3i,kSr[3],kSi[3]) - G03*h30r - G13*h31r - G23*h32r); \
    float e3i = beta_[P][3] * (via[P][3] - CMI(A3r,A3i,kSr[3],kSi[3]) - G03*h30i - G13*h31i - G23*h32i); \
    if (lane == 0) { \
        int rq_ = rh0 + (IT) * 4 * H_; \
        float y0r = CMR(a0r,a0i,qSr[0],qSi[0]) + P00*e0r; \
        float y0i = CMI(a0r,a0i,qSr[0],qSi[0]) + P00*e0i; \
        float y1r = CMR(A1r,A1i,qSr[1],qSi[1]) + P01*h10r + P11*e1r; \
        float y1i = CMI(A1r,A1i,qSr[1],qSi[1]) + P01*h10i + P11*e1i; \
        float y2r = CMR(A2r,A2i,qSr[2],qSi[2]) + P02*h20r + P12*h21r + P22*e2r; \
        float y2i = CMI(A2r,A2i,qSr[2],qSi[2]) + P02*h20i + P12*h21i + P22*e2i; \
        float y3r = CMR(A3r,A3i,qSr[3],qSi[3]) + P03*h30r + P13*h31r + P23*h32r + P33*e3r; \
        float y3i = CMI(A3r,A3i,qSr[3],qSi[3]) + P03*h30i + P13*h31i + P23*h32i + P33*e3i; \
        float s0 = sc*P00*P00, s1 = sc*P11*P11, s2 = sc*P22*P22, s3 = sc*P33*P33; \
        *(float2*)(g_retr + (size_t)rq_ * N_ + 2*nh) = \
            make_float2((y0r + s0*vra[P][0]) * sela[P][0], (y0i + s0*via[P][0]) * sela[P][0]); \
        *(float2*)(g_retr + (size_t)(rq_ + H_) * N_ + 2*nh) = \
            make_float2((y1r + s1*vra[P][1]) * sela[P][1], (y1i + s1*via[P][1]) * sela[P][1]); \
        *(float2*)(g_retr + (size_t)(rq_ + 2*H_) * N_ + 2*nh) = \
            make_float2((y2r + s2*vra[P][2]) * sela[P][2], (y2i + s2*via[P][2]) * sela[P][2]); \
        *(float2*)(g_retr + (size_t)(rq_ + 3*H_) * N_ + 2*nh) = \
            make_float2((y3r + s3*vra[P][3]) * sela[P][3], (y3i + s3*via[P][3]) * sela[P][3]); \
    } \
    u64 A3r2 = pk2(A3r, A3r), A3i2 = pk2(A3i, A3i), A3in2 = pk2(-A3i, -A3i); \
    u64 c0r2 = pk2(h30r, h30r), c0i2 = pk2(h30i, h30i); \
    u64 c1r2 = pk2(h31r, h31r), c1i2 = pk2(h31i, h31i); \
    u64 c2r2 = pk2(h32r, h32r), c2i2 = pk2(h32i, h32i); \
    u64 c3r2 = pk2(e3r, e3r),   c3i2 = pk2(e3i, e3i); \
    _Pragma("unroll") \
    for (int j_ = 0; j_ < 2; j_++) { \
        u64 rre = fma2(A3r2, Sre2[j_], mul2(A3in2, Sim2[j_])); \
        u64 rim = fma2(A3r2, Sim2[j_], mul2(A3i2, Sre2[j_])); \
        rre = fma2(c0r2, kx[P][0][j_], rre); rim = fma2(c0i2, kx[P][0][j_], rim); \
        rre = fma2(c1r2, kx[P][1][j_], rre); rim = fma2(c1i2, kx[P][1][j_], rim); \
        rre = fma2(c2r2, kx[P][2][j_], rre); rim = fma2(c2i2, kx[P][2][j_], rim); \
        Sre2[j_] = fma2(c3r2, kx[P][3][j_], rre); \
        Sim2[j_] = fma2(c3i2, kx[P][3][j_], rim); \
    } }

__global__ __launch_bounds__(32) void k_scan(const float* __restrict__ scp) {
    int wi = blockIdx.x;               // 0..255
    int nh = wi & 15;
    int h  = (wi >> 4) & 7;
    int b  = wi >> 7;
    int lane = threadIdx.x;
    float sc = scp[0];

    u64 Sre2[2], Sim2[2];
    Sre2[0] = Sre2[1] = 0ull;
    Sim2[0] = Sim2[1] = 0ull;

    int rh0 = (b * L_) * H_ + h;
    int bofs = b * (L_ / 4);

    u64 kx[2][4][2], qx[2][4][2];
    float ara[2][4], aia[2][4], vra[2][4], via[2][4], beta_[2][4], sela[2][4];
    float4 cdA[2][4];

    LOADQ(0, 0)

    for (int it = 0; it < L_/4; it += 2) {
        QSTEP(0, it)
        QSTEP(1, it + 1)
    }
}

// ---------------- group-norm apply + silu(z) gate + Dskip, float4 ----------------
__global__ void k_post(const float* __restrict__ gnw, const float* __restrict__ gnb,
                       const float* __restrict__ dskip) {
    int i = blockIdx.x * 256 + threadIdx.x;     // over ROWS_ * DI_/4
    if (i >= ROWS_ * (DI_ / 4)) return;
    int m = i >> 8;
    int c4 = (i & 255) << 2;
    int b = m >> 10;
    int bg = b * 8 + (c4 >> 7);
    const float inv = 1.0f / (float)(L_ * 128);
    float mean = g_gnsum[bg] * inv;
    float var = g_gnsq[bg] * inv - mean * mean;
    float rs = rsqrtf(var + 1e-5f);
    float4 yv = *(const float4*)(g_y + (size_t)m * DI_ + c4);
    float4 wv = *(const float4*)(gnw + c4);
    float4 bv = *(const float4*)(gnb + c4);
    float4 zv = *(const float4*)(g_proj + (size_t)m * NPROJ + c4);
    float4 dv = *(const float4*)(dskip + c4);
    float4 xv = *(const float4*)(g_xconv + (size_t)m * DI_ + c4);
    float4 o;
    o.x = ((yv.x - mean) * rs * wv.x + bv.x) * siluf(zv.x) + dv.x * xv.x;
    o.y = ((yv.y - mean) * rs * wv.y + bv.y) * siluf(zv.y) + dv.y * xv.y;
    o.z = ((yv.z - mean) * rs * wv.z + bv.z) * siluf(zv.z) + dv.z * xv.z;
    o.w = ((yv.w - mean) * rs * wv.w + bv.w) * siluf(zv.w) + dv.w * xv.w;
    *(float4*)(g_y2 + (size_t)m * DI_ + c4) = o;
}

// ---------------- launcher ----------------
extern "C" void kernel_launch(void* const* d_in, const int* in_sizes, int n_in,
                              void* d_out, int out_size) {
    const float* x        = (const float*)d_in[0];
    const float* v_first  = (const float*)d_in[1];
    const float* norm_w   = (const float*)d_in[2];
    const float* in_proj_w= (const float*)d_in[3];
    const float* in_proj_b= (const float*)d_in[4];
    const float* conv_w   = (const float*)d_in[5];
    const float* conv_b   = (const float*)d_in[6];
    const float* gate_w   = (const float*)d_in[7];
    const float* gate_b   = (const float*)d_in[8];
    const float* log_dt   = (const float*)d_in[9];
    const float* q_w      = (const float*)d_in[10];
    const float* readout_w= (const float*)d_in[11];
    const float* out_w    = (const float*)d_in[12];
    const float* gn_w     = (const float*)d_in[13];
    const float* gn_b     = (const float*)d_in[14];
    const float* dskip    = (const float*)d_in[15];
    const float* vrg      = (const float*)d_in[16];
    const float* shortcut = (const float*)d_in[17];
    float* out = (float*)d_out;

    float *p_xn, *p_proj, *p_xc, *p_Q, *p_retr, *p_y, *p_y2, *p_gates, *p_gnsum, *p_gnsq;
    int* p_qflag;
    cudaGetSymbolAddress((void**)&p_xn,    g_xn);
    cudaGetSymbolAddress((void**)&p_proj,  g_proj);
    cudaGetSymbolAddress((void**)&p_xc,    g_xconv);
    cudaGetSymbolAddress((void**)&p_gates, g_gates);
    cudaGetSymbolAddress((void**)&p_Q,     g_Q);
    cudaGetSymbolAddress((void**)&p_retr,  g_retr);
    cudaGetSymbolAddress((void**)&p_y,     g_y);
    cudaGetSymbolAddress((void**)&p_y2,    g_y2);
    cudaGetSymbolAddress((void**)&p_gnsum, g_gnsum);
    cudaGetSymbolAddress((void**)&p_gnsq,  g_gnsq);
    cudaGetSymbolAddress((void**)&p_qflag, g_qflag);

    const int smem128 = STAGES * (128 + 128) * SSTR * 4;  // 61440
    const int smem64  = STAGES * (128 + 64)  * SSTR * 4;  // 46080
    cudaFuncSetAttribute(k_gemm_tf32<128>, cudaFuncAttributeMaxDynamicSharedMemorySize, smem128);
    cudaFuncSetAttribute(k_gemm_tf32<64>,  cudaFuncAttributeMaxDynamicSharedMemorySize, smem64);

    // 0) init (qflag=1, gn stats)
    k_init<<<1, 32>>>();
    // 1) fused rmsnorm + qcheck
    k_normcheck<<<ROWS_ + (DI_ * DI_ / 4 + 127) / 128, 128>>>(x, norm_w, q_w);
    // 2) in_proj
    k_gemm_tf32<128><<<dim3((NPROJ + 127) / 128, ROWS_ / 128), 256, smem128>>>(p_xn, in_proj_w, in_proj_b, nullptr, p_proj, ROWS_, NPROJ, DM_, nullptr, nullptr, nullptr);
    // 3) conv + silu (float4)
    k_conv<<<(ROWS_ * (DI_/4)) / 256, 256>>>(conv_w, conv_b);
    // 4) gates
    k_gemm_tf32<64><<<dim3((NGATE + 63) / 64, ROWS_ / 128), 256, smem64>>>(p_xc, gate_w, gate_b, nullptr, p_gates, ROWS_, NGATE, DI_, nullptr, nullptr, nullptr);
    // 5) Q (skipped when q_w == I)
    k_gemm_tf32<128><<<dim3(DI_ / 128, ROWS_ / 128), 256, smem128>>>(p_xc, q_w, nullptr, nullptr, p_Q, ROWS_, DI_, DI_, p_qflag, nullptr, nullptr);
    // 6) fused dynamics + l2norm + quad Gram scalars
    k_dynl2<<<NDYN + NL2, 256>>>(v_first, log_dt, vrg);
    // 7) scan (WY-4)
    k_scan<<<256, 32>>>(shortcut);
    // 8) readout + fused gn stats
    k_gemm_tf32<128><<<dim3(DI_ / 128, ROWS_ / 128), 256, smem128>>>(p_retr, readout_w, nullptr, nullptr, p_y, ROWS_, DI_, H_ * N_, nullptr, p_gnsum, p_gnsq);
    // 9) gn apply + gate + skip (float4)
    k_post<<<(ROWS_ * (DI_/4)) / 256, 256>>>(gn_w, gn_b, dskip);
    // 10) out GEMM + residual
    k_gemm_tf32<64><<<dim3(DM_ / 64, ROWS_ / 128), 256, smem64>>>(p_y2, out_w, nullptr, x, out, ROWS_, DM_, DI_, nullptr, nullptr, nullptr);
}